// round 16
// baseline (speedup 1.0000x reference)
#include <cuda_runtime.h>
#include <cuda_bf16.h>
#include <cstdint>

#define IN_CH   256
#define OUT_CH  256
#define NTASKS  64
#define WSIZE   (OUT_CH * IN_CH)
#define FULL_EMBED (WSIZE + OUT_CH)
#define BMAX    4096
#define NCOLS   64              // output cols per CTA
#define MT      32              // rows per M-tile
#define THREADS 256
#define SCAN_IT (BMAX / THREADS)   // 16

// bf16 row stride: 264 elements = 528 bytes (conflict-free ldmatrix phases)
#define RSTRIDE_B 528

// smem byte offsets
#define SM_WHI  0
#define SM_WLO  (SM_WHI + NCOLS * RSTRIDE_B)        // 33792
#define SM_XHI  (SM_WLO + NCOLS * RSTRIDE_B)        // 67584
#define SM_XLO  (SM_XHI + MT * RSTRIDE_B)           // 84480
#define SM_BIAS (SM_XLO + MT * RSTRIDE_B)           // 101376
#define SM_LIST (SM_BIAS + NCOLS * 4)               // 101632 (uint16 x 4096)
#define SM_CNT  (SM_LIST + BMAX * 2)                // 109824
#define SMEM_B  (SM_CNT + 16)                       // 109840 (~107.3KB -> 2 CTAs/SM)

// ================= helpers =================================================
__device__ __forceinline__ uint32_t smem_u32(const void* p) {
    uint32_t a;
    asm("{ .reg .u64 t; cvta.to.shared.u64 t, %1; cvt.u32.u64 %0, t; }" : "=r"(a) : "l"(p));
    return a;
}
__device__ __forceinline__ uint32_t pack_bf16(float a, float b) {
    __nv_bfloat162 t = __floats2bfloat162_rn(a, b);
    return *(uint32_t*)&t;
}
__device__ __forceinline__ float bf_hi(float x) {
    return __bfloat162float(__float2bfloat16(x));
}

#define LDSM_X4(r0, r1, r2, r3, addr)                                      \
    asm volatile("ldmatrix.sync.aligned.m8n8.x4.shared.b16 {%0,%1,%2,%3}, [%4];" \
        : "=r"(r0), "=r"(r1), "=r"(r2), "=r"(r3) : "r"(addr))

#define MMA_BF16(c, a0, a1, a2, a3, b0, b1)                                \
    asm volatile("mma.sync.aligned.m16n8k16.row.col.f32.bf16.bf16.f32 "    \
        "{%0,%1,%2,%3}, {%4,%5,%6,%7}, {%8,%9}, {%0,%1,%2,%3};"            \
        : "+f"((c)[0]), "+f"((c)[1]), "+f"((c)[2]), "+f"((c)[3])           \
        : "r"(a0), "r"(a1), "r"(a2), "r"(a3), "r"(b0), "r"(b1))

// W convert+STS for one column of this warp
__device__ __forceinline__ void w_sts(char* smem, int c, int lane,
                                      float4 a, float4 b) {
    char* whi = smem + SM_WHI + c * RSTRIDE_B;
    char* wlo = smem + SM_WLO + c * RSTRIDE_B;
    *(uint2*)(whi + lane * 8) =
        make_uint2(pack_bf16(a.x, a.y), pack_bf16(a.z, a.w));
    *(uint2*)(whi + 256 + lane * 8) =
        make_uint2(pack_bf16(b.x, b.y), pack_bf16(b.z, b.w));
    *(uint2*)(wlo + lane * 8) =
        make_uint2(pack_bf16(a.x - bf_hi(a.x), a.y - bf_hi(a.y)),
                   pack_bf16(a.z - bf_hi(a.z), a.w - bf_hi(a.w)));
    *(uint2*)(wlo + 256 + lane * 8) =
        make_uint2(pack_bf16(b.x - bf_hi(b.x), b.y - bf_hi(b.y)),
                   pack_bf16(b.z - bf_hi(b.z), b.w - bf_hi(b.w)));
}

// ================= main: CTA = (task, 64-col chunk), fused scan ============
__global__ __launch_bounds__(THREADS, 2)
void affine_hmma_kernel(const float* __restrict__ inputs,
                        const int* __restrict__ task_ids,
                        const float* __restrict__ te,
                        float* __restrict__ out,
                        int B) {
    extern __shared__ char smem[];
    const uint32_t sb = smem_u32(smem);
    float* bias_sm = (float*)(smem + SM_BIAS);
    unsigned short* list = (unsigned short*)(smem + SM_LIST);
    int* s_n = (int*)(smem + SM_CNT);

    const int task    = blockIdx.y;
    const int colBase = blockIdx.x * NCOLS;
    const int tid     = threadIdx.x;
    const int lane    = tid & 31;
    const int wid     = tid >> 5;      // 0..7

    if (tid == 0) s_n[0] = 0;
    __syncthreads();

    const float* emb = te + (size_t)task * FULL_EMBED;

    // ---- W batch 1: issue 8 LDG.128 (cols w, w+8, w+16, w+24) ----
    float4 wa0[4], wa1[4];
    #pragma unroll
    for (int rr = 0; rr < 4; rr++) {
        const int c = wid + rr * 8;
        const float4* wg = (const float4*)(emb + (size_t)(colBase + c) * IN_CH);
        wa0[rr] = wg[lane];
        wa1[rr] = wg[lane + 32];
    }

    // ---- scan: batch ids, all ballots, ONE atomic per warp ----
    {
        int myid[SCAN_IT];
        #pragma unroll
        for (int j = 0; j < SCAN_IT; j++) {
            const int i = tid + j * THREADS;
            myid[j] = (i < B) ? task_ids[i] : -1;
        }
        unsigned bal[SCAN_IT];
        int wtot = 0;
        #pragma unroll
        for (int j = 0; j < SCAN_IT; j++) {
            bal[j] = __ballot_sync(0xFFFFFFFFu, myid[j] == task);
            wtot += __popc(bal[j]);
        }
        int base = 0;
        if (lane == 0 && wtot) base = atomicAdd(s_n, wtot);
        base = __shfl_sync(0xFFFFFFFFu, base, 0);
        #pragma unroll
        for (int j = 0; j < SCAN_IT; j++) {
            if (myid[j] == task) {
                const int pos = base + __popc(bal[j] & ((1u << lane) - 1u));
                list[pos] = (unsigned short)(tid + j * THREADS);
            }
            base += __popc(bal[j]);
        }
    }

    // ---- bias ----
    if (tid < NCOLS) bias_sm[tid] = emb[WSIZE + colBase + tid];

    // ---- W batch 2 issue, convert batch 1, convert batch 2 ----
    {
        float4 wb0[4], wb1[4];
        #pragma unroll
        for (int rr = 0; rr < 4; rr++) {
            const int c = wid + 32 + rr * 8;          // cols w+32 .. w+56
            const float4* wg = (const float4*)(emb + (size_t)(colBase + c) * IN_CH);
            wb0[rr] = wg[lane];
            wb1[rr] = wg[lane + 32];
        }
        #pragma unroll
        for (int rr = 0; rr < 4; rr++)
            w_sts(smem, wid + rr * 8, lane, wa0[rr], wa1[rr]);
        #pragma unroll
        for (int rr = 0; rr < 4; rr++)
            w_sts(smem, wid + 32 + rr * 8, lane, wb0[rr], wb1[rr]);
    }
    __syncthreads();
    const int n = s_n[0];

    // ---- warp tiling: 2 (M) x 4 (N); warp = m16 x n16 (R10/R11-verified) ----
    const int warp_m = wid >> 2;          // 0..1
    const int warp_n = wid & 3;           // 0..3
    const int mrow0  = warp_m * 16;
    const int ncol0  = warp_n * 16;       // within the 64-col chunk
    const int g      = lane >> 2;
    const int tg     = lane & 3;

    const int a_row  = mrow0 + ((lane >> 3) & 1) * 8 + (lane & 7);
    const uint32_t a_off = (uint32_t)a_row * RSTRIDE_B + ((lane >> 4) * 16);
    const int b_col  = ncol0 + (lane >> 4) * 8 + (lane & 7);
    const uint32_t b_koff = ((lane >> 3) & 1) * 16;
    const uint32_t bh = sb + SM_WHI + (uint32_t)b_col * RSTRIDE_B + b_koff;
    const uint32_t bl = bh + (SM_WLO - SM_WHI);
    const uint32_t ahi = sb + SM_XHI + a_off;
    const uint32_t alo = sb + SM_XLO + a_off;

    // ---- loop over 32-row tiles ----
    for (int m0 = 0; m0 < n; m0 += MT) {
        if (m0) __syncthreads();

        // stage X hi/lo: each warp 4 rows; valid rows only (stale data masked)
        {
            float4 v0[4], v1[4];
            int nv = 0;
            #pragma unroll
            for (int rr = 0; rr < 4; rr++) {
                const int row = m0 + wid * 4 + rr;
                if (row < n) {
                    const float4* xg =
                        (const float4*)(inputs + (size_t)list[row] * IN_CH);
                    v0[rr] = xg[lane];
                    v1[rr] = xg[lane + 32];
                    nv = rr + 1;
                }
            }
            for (int rr = 0; rr < nv; rr++) {
                const int r = wid * 4 + rr;
                char* xhi = smem + SM_XHI + r * RSTRIDE_B;
                char* xlo = smem + SM_XLO + r * RSTRIDE_B;
                float4 a = v0[rr], b = v1[rr];
                *(uint2*)(xhi + lane * 8) =
                    make_uint2(pack_bf16(a.x, a.y), pack_bf16(a.z, a.w));
                *(uint2*)(xhi + 256 + lane * 8) =
                    make_uint2(pack_bf16(b.x, b.y), pack_bf16(b.z, b.w));
                *(uint2*)(xlo + lane * 8) =
                    make_uint2(pack_bf16(a.x - bf_hi(a.x), a.y - bf_hi(a.y)),
                               pack_bf16(a.z - bf_hi(a.z), a.w - bf_hi(a.w)));
                *(uint2*)(xlo + 256 + lane * 8) =
                    make_uint2(pack_bf16(b.x - bf_hi(b.x), b.y - bf_hi(b.y)),
                               pack_bf16(b.z - bf_hi(b.z), b.w - bf_hi(b.w)));
            }
        }
        __syncthreads();

        // warp-level tail skip
        if (m0 + mrow0 < n) {
            float acc[2][4];
            #pragma unroll
            for (int f = 0; f < 2; f++)
                #pragma unroll
                for (int j = 0; j < 4; j++) acc[f][j] = 0.f;

            #pragma unroll 4
            for (int ks = 0; ks < IN_CH; ks += 16) {
                const uint32_t kb = ks * 2;
                uint32_t aH0, aH1, aH2, aH3, aL0, aL1, aL2, aL3;
                uint32_t h0, h1, h2, h3, l0, l1, l2, l3;
                LDSM_X4(aH0, aH1, aH2, aH3, ahi + kb);
                LDSM_X4(aL0, aL1, aL2, aL3, alo + kb);
                LDSM_X4(h0, h1, h2, h3, bh + kb);
                LDSM_X4(l0, l1, l2, l3, bl + kb);
                // hi * hi
                MMA_BF16(acc[0], aH0, aH1, aH2, aH3, h0, h1);
                MMA_BF16(acc[1], aH0, aH1, aH2, aH3, h2, h3);
                // hi * lo
                MMA_BF16(acc[0], aH0, aH1, aH2, aH3, l0, l1);
                MMA_BF16(acc[1], aH0, aH1, aH2, aH3, l2, l3);
                // lo * hi
                MMA_BF16(acc[0], aL0, aL1, aL2, aL3, h0, h1);
                MMA_BF16(acc[1], aL0, aL1, aL2, aL3, h2, h3);
            }

            // ---- epilogue (R10-verified frag->col map) ----
            const int row0 = m0 + mrow0 + g;
            const int row1 = row0 + 8;
            #pragma unroll
            for (int f = 0; f < 2; f++) {
                const int cloc = ncol0 + f * 8 + tg * 2;
                const float b0 = bias_sm[cloc];
                const float b1 = bias_sm[cloc + 1];
                if (row0 < n) {
                    float* p = out + (size_t)list[row0] * OUT_CH + colBase + cloc;
                    *(float2*)p = make_float2(acc[f][0] + b0, acc[f][1] + b1);
                }
                if (row1 < n) {
                    float* p = out + (size_t)list[row1] * OUT_CH + colBase + cloc;
                    *(float2*)p = make_float2(acc[f][2] + b0, acc[f][3] + b1);
                }
            }
        }
    }
}

// ================= launch ==================================================
extern "C" void kernel_launch(void* const* d_in, const int* in_sizes, int n_in,
                              void* d_out, int out_size) {
    const float* inputs   = (const float*)d_in[0];
    const int*   task_ids = (const int*)d_in[1];   // JAX x64 disabled -> int32
    const float* te       = (const float*)d_in[2];
    float*       out      = (float*)d_out;
    int B = in_sizes[1];

    cudaFuncSetAttribute(affine_hmma_kernel,
                         cudaFuncAttributeMaxDynamicSharedMemorySize, SMEM_B);
    dim3 grid(OUT_CH / NCOLS, NTASKS, 1);   // (4, 64) = 256 CTAs, 2/SM
    affine_hmma_kernel<<<grid, THREADS, SMEM_B>>>(inputs, task_ids, te, out, B);
}

// round 17
// speedup vs baseline: 1.3734x; 1.3734x over previous
#include <cuda_runtime.h>
#include <cuda_fp16.h>
#include <cstdint>

#define IN_CH   256
#define OUT_CH  256
#define NTASKS  64
#define WSIZE   (OUT_CH * IN_CH)
#define FULL_EMBED (WSIZE + OUT_CH)
#define BMAX    4096
#define NCOLS   128             // output cols per CTA
#define MT      64              // rows per M-tile
#define THREADS 512
#define SCAN_IT (BMAX / (4 * THREADS))   // 2 (int4 loads)

// fp16 row stride: 264 elements = 528 bytes (conflict-free ldmatrix phases)
#define RSTRIDE_B 528

// smem byte offsets
#define SM_WHI  0
#define SM_WLO  (SM_WHI + NCOLS * RSTRIDE_B)        // 67584
#define SM_XHI  (SM_WLO + NCOLS * RSTRIDE_B)        // 135168
#define SM_BIAS (SM_XHI + MT * RSTRIDE_B)           // 168960
#define SM_LIST (SM_BIAS + NCOLS * 4)               // 169472 (uint16 x 4096)
#define SM_CNT  (SM_LIST + BMAX * 2)                // 177664
#define SMEM_B  (SM_CNT + 16)                       // ~173.5KB, 1 CTA/SM

// ================= helpers =================================================
__device__ __forceinline__ uint32_t smem_u32(const void* p) {
    uint32_t a;
    asm("{ .reg .u64 t; cvta.to.shared.u64 t, %1; cvt.u32.u64 %0, t; }" : "=r"(a) : "l"(p));
    return a;
}
__device__ __forceinline__ uint32_t pack_fp16(float a, float b) {
    __half2 t = __floats2half2_rn(a, b);
    return *(uint32_t*)&t;
}
__device__ __forceinline__ float hp_hi(float x) {
    return __half2float(__float2half_rn(x));
}

#define LDSM_X4(r0, r1, r2, r3, addr)                                      \
    asm volatile("ldmatrix.sync.aligned.m8n8.x4.shared.b16 {%0,%1,%2,%3}, [%4];" \
        : "=r"(r0), "=r"(r1), "=r"(r2), "=r"(r3) : "r"(addr))

#define MMA_FP16(c, a0, a1, a2, a3, b0, b1)                                \
    asm volatile("mma.sync.aligned.m16n8k16.row.col.f32.f16.f16.f32 "      \
        "{%0,%1,%2,%3}, {%4,%5,%6,%7}, {%8,%9}, {%0,%1,%2,%3};"            \
        : "+f"((c)[0]), "+f"((c)[1]), "+f"((c)[2]), "+f"((c)[3])           \
        : "r"(a0), "r"(a1), "r"(a2), "r"(a3), "r"(b0), "r"(b1))

// W convert+STS for one column batch of this warp (hi/lo fp16)
__device__ __forceinline__ void w_sts(char* smem, int c, int lane,
                                      float4 a, float4 b) {
    char* whi = smem + SM_WHI + c * RSTRIDE_B;
    char* wlo = smem + SM_WLO + c * RSTRIDE_B;
    *(uint2*)(whi + lane * 8) =
        make_uint2(pack_fp16(a.x, a.y), pack_fp16(a.z, a.w));
    *(uint2*)(whi + 256 + lane * 8) =
        make_uint2(pack_fp16(b.x, b.y), pack_fp16(b.z, b.w));
    *(uint2*)(wlo + lane * 8) =
        make_uint2(pack_fp16(a.x - hp_hi(a.x), a.y - hp_hi(a.y)),
                   pack_fp16(a.z - hp_hi(a.z), a.w - hp_hi(a.w)));
    *(uint2*)(wlo + 256 + lane * 8) =
        make_uint2(pack_fp16(b.x - hp_hi(b.x), b.y - hp_hi(b.y)),
                   pack_fp16(b.z - hp_hi(b.z), b.w - hp_hi(b.w)));
}

// ================= main: CTA = (task, 128-col chunk), fused scan ===========
__global__ __launch_bounds__(THREADS, 1)
void affine_hmma_kernel(const float* __restrict__ inputs,
                        const int* __restrict__ task_ids,
                        const float* __restrict__ te,
                        float* __restrict__ out,
                        int B) {
    extern __shared__ char smem[];
    const uint32_t sb = smem_u32(smem);
    float* bias_sm = (float*)(smem + SM_BIAS);
    unsigned short* list = (unsigned short*)(smem + SM_LIST);
    int* s_n = (int*)(smem + SM_CNT);

    const int task    = blockIdx.y;
    const int colBase = blockIdx.x * NCOLS;
    const int tid     = threadIdx.x;
    const int lane    = tid & 31;
    const int wid     = tid >> 5;      // 0..15

    if (tid == 0) s_n[0] = 0;
    __syncthreads();

    const float* emb = te + (size_t)task * FULL_EMBED;

    // ---- W batch 1: issue 8 LDG.128 (cols w, w+16, w+32, w+48) ----
    float4 wa0[4], wa1[4];
    #pragma unroll
    for (int rr = 0; rr < 4; rr++) {
        const int c = wid + rr * 16;
        const float4* wg = (const float4*)(emb + (size_t)(colBase + c) * IN_CH);
        wa0[rr] = wg[lane];
        wa1[rr] = wg[lane + 32];
    }

    // ---- scan: int4 id loads, all ballots, ONE atomic per warp ----
    {
        int4 idv[SCAN_IT];
        #pragma unroll
        for (int j = 0; j < SCAN_IT; j++)
            idv[j] = ((const int4*)task_ids)[tid + j * THREADS];

        unsigned bal[SCAN_IT][4];
        int wtot = 0;
        #pragma unroll
        for (int j = 0; j < SCAN_IT; j++) {
            bal[j][0] = __ballot_sync(0xFFFFFFFFu, idv[j].x == task);
            bal[j][1] = __ballot_sync(0xFFFFFFFFu, idv[j].y == task);
            bal[j][2] = __ballot_sync(0xFFFFFFFFu, idv[j].z == task);
            bal[j][3] = __ballot_sync(0xFFFFFFFFu, idv[j].w == task);
            wtot += __popc(bal[j][0]) + __popc(bal[j][1])
                  + __popc(bal[j][2]) + __popc(bal[j][3]);
        }
        int base = 0;
        if (lane == 0 && wtot) base = atomicAdd(s_n, wtot);
        base = __shfl_sync(0xFFFFFFFFu, base, 0);
        const unsigned lmask = (1u << lane) - 1u;
        #pragma unroll
        for (int j = 0; j < SCAN_IT; j++) {
            const int i4 = (tid + j * THREADS) * 4;
            const int cmp[4] = { idv[j].x, idv[j].y, idv[j].z, idv[j].w };
            #pragma unroll
            for (int c = 0; c < 4; c++) {
                if (cmp[c] == task)
                    list[base + __popc(bal[j][c] & lmask)] = (unsigned short)(i4 + c);
                base += __popc(bal[j][c]);
            }
        }
    }

    // ---- bias ----
    if (tid < NCOLS) bias_sm[tid] = emb[WSIZE + colBase + tid];

    // ---- W batch 2 issue, convert batch 1, convert batch 2 ----
    {
        float4 wb0[4], wb1[4];
        #pragma unroll
        for (int rr = 0; rr < 4; rr++) {
            const int c = wid + (rr + 4) * 16;        // cols w+64 .. w+112
            const float4* wg = (const float4*)(emb + (size_t)(colBase + c) * IN_CH);
            wb0[rr] = wg[lane];
            wb1[rr] = wg[lane + 32];
        }
        #pragma unroll
        for (int rr = 0; rr < 4; rr++)
            w_sts(smem, wid + rr * 16, lane, wa0[rr], wa1[rr]);
        #pragma unroll
        for (int rr = 0; rr < 4; rr++)
            w_sts(smem, wid + (rr + 4) * 16, lane, wb0[rr], wb1[rr]);
    }
    __syncthreads();
    const int n = s_n[0];

    // ---- warp tiling: 4 (M) x 4 (N); warp = m16 x n32 (R7-verified maps) ----
    const int warp_m = wid >> 2;          // 0..3
    const int warp_n = wid & 3;           // 0..3
    const int mrow0  = warp_m * 16;
    const int ncol0  = warp_n * 32;
    const int g      = lane >> 2;
    const int tg     = lane & 3;

    const int a_row  = mrow0 + ((lane >> 3) & 1) * 8 + (lane & 7);
    const uint32_t a_off = (uint32_t)a_row * RSTRIDE_B + ((lane >> 4) * 16);
    const int b_col0 = ncol0 + (lane >> 4) * 8 + (lane & 7);
    const uint32_t b_koff = ((lane >> 3) & 1) * 16;
    const uint32_t bh0 = sb + SM_WHI + (uint32_t)b_col0 * RSTRIDE_B + b_koff;
    const uint32_t bh1 = bh0 + 16 * RSTRIDE_B;
    const uint32_t bl0 = bh0 + (SM_WLO - SM_WHI);
    const uint32_t bl1 = bh1 + (SM_WLO - SM_WHI);
    const uint32_t ahi = sb + SM_XHI + a_off;

    // ---- loop over 64-row tiles ----
    for (int m0 = 0; m0 < n; m0 += MT) {
        if (m0) __syncthreads();

        // stage X (fp16 hi only): each warp 4 rows; valid rows only
        {
            float4 v0[4], v1[4];
            int nv = 0;
            #pragma unroll
            for (int rr = 0; rr < 4; rr++) {
                const int row = m0 + wid * 4 + rr;
                if (row < n) {
                    const float4* xg =
                        (const float4*)(inputs + (size_t)list[row] * IN_CH);
                    v0[rr] = xg[lane];
                    v1[rr] = xg[lane + 32];
                    nv = rr + 1;
                }
            }
            for (int rr = 0; rr < nv; rr++) {
                const int r = wid * 4 + rr;
                char* xhi = smem + SM_XHI + r * RSTRIDE_B;
                float4 a = v0[rr], b = v1[rr];
                *(uint2*)(xhi + lane * 8) =
                    make_uint2(pack_fp16(a.x, a.y), pack_fp16(a.z, a.w));
                *(uint2*)(xhi + 256 + lane * 8) =
                    make_uint2(pack_fp16(b.x, b.y), pack_fp16(b.z, b.w));
            }
        }
        __syncthreads();

        // warp-level tail skip
        if (m0 + mrow0 < n) {
            float acc[4][4];
            #pragma unroll
            for (int f = 0; f < 4; f++)
                #pragma unroll
                for (int j = 0; j < 4; j++) acc[f][j] = 0.f;

            #pragma unroll 4
            for (int ks = 0; ks < IN_CH; ks += 16) {
                const uint32_t kb = ks * 2;
                uint32_t a0, a1, a2, a3;
                uint32_t h00, h01, h02, h03, h10, h11, h12, h13;
                uint32_t l00, l01, l02, l03, l10, l11, l12, l13;
                LDSM_X4(a0, a1, a2, a3, ahi + kb);
                LDSM_X4(h00, h01, h02, h03, bh0 + kb);
                LDSM_X4(h10, h11, h12, h13, bh1 + kb);
                LDSM_X4(l00, l01, l02, l03, bl0 + kb);
                LDSM_X4(l10, l11, l12, l13, bl1 + kb);
                // x * W_hi
                MMA_FP16(acc[0], a0, a1, a2, a3, h00, h01);
                MMA_FP16(acc[1], a0, a1, a2, a3, h02, h03);
                MMA_FP16(acc[2], a0, a1, a2, a3, h10, h11);
                MMA_FP16(acc[3], a0, a1, a2, a3, h12, h13);
                // x * W_lo
                MMA_FP16(acc[0], a0, a1, a2, a3, l00, l01);
                MMA_FP16(acc[1], a0, a1, a2, a3, l02, l03);
                MMA_FP16(acc[2], a0, a1, a2, a3, l10, l11);
                MMA_FP16(acc[3], a0, a1, a2, a3, l12, l13);
            }

            // ---- epilogue (R7-verified frag->col map) ----
            const int row0 = m0 + mrow0 + g;
            const int row1 = row0 + 8;
            #pragma unroll
            for (int f = 0; f < 4; f++) {
                const int cloc = ncol0 + ((f & 1) ? 8 : 0) + ((f >> 1) ? 16 : 0) + tg * 2;
                const float b0 = bias_sm[cloc];
                const float b1 = bias_sm[cloc + 1];
                if (row0 < n) {
                    float* p = out + (size_t)list[row0] * OUT_CH + colBase + cloc;
                    *(float2*)p = make_float2(acc[f][0] + b0, acc[f][1] + b1);
                }
                if (row1 < n) {
                    float* p = out + (size_t)list[row1] * OUT_CH + colBase + cloc;
                    *(float2*)p = make_float2(acc[f][2] + b0, acc[f][3] + b1);
                }
            }
        }
    }
}

// ================= launch ==================================================
extern "C" void kernel_launch(void* const* d_in, const int* in_sizes, int n_in,
                              void* d_out, int out_size) {
    const float* inputs   = (const float*)d_in[0];
    const int*   task_ids = (const int*)d_in[1];   // JAX x64 disabled -> int32
    const float* te       = (const float*)d_in[2];
    float*       out      = (float*)d_out;
    int B = in_sizes[1];

    cudaFuncSetAttribute(affine_hmma_kernel,
                         cudaFuncAttributeMaxDynamicSharedMemorySize, SMEM_B);
    dim3 grid(OUT_CH / NCOLS, NTASKS, 1);   // (2, 64) = 128 CTAs, single launch
    affine_hmma_kernel<<<grid, THREADS, SMEM_B>>>(inputs, task_ids, te, out, B);
}